// round 3
// baseline (speedup 1.0000x reference)
#include <cuda_runtime.h>
#include <cstdint>

#define BB   64
#define SS   2048
#define HH   256
#define G4   1024           // 4*H
#define MTOT (BB*SS)        // 131072

// ---------------- scratch (device globals; no allocations allowed) -----------
__device__ float    g_xproj[(size_t)MTOT * G4];   // [B*S, 4H]  (512 MB)
__device__ float    g_h[2][BB*HH];                // double-buffered hidden state
__device__ unsigned g_cnt;                        // barrier arrive counter
__device__ unsigned g_gen;                        // barrier generation (monotone)

// ======================= Phase 1: x_proj GEMM ================================
// C[m,n] = sum_k x[m,k] * W_ih[n,k] + (b_ih[n]+b_hh[n]);  M=131072,N=1024,K=256
#define BM  64
#define BN  64
#define BK  32
#define PAD 68   // 64 + 4, keeps float4 alignment, spreads store banks

__global__ __launch_bounds__(256) void xproj_kernel(
    const float* __restrict__ x, const float* __restrict__ W_ih,
    const float* __restrict__ b_ih, const float* __restrict__ b_hh)
{
    __shared__ float As[BK * PAD];   // [k][m]
    __shared__ float Bs[BK * PAD];   // [k][n]
    __shared__ float bias_s[BN];

    const int tid = threadIdx.x;
    const int tx = tid & 15, ty = tid >> 4;
    const long m0 = (long)blockIdx.y * BM;
    const int  n0 = blockIdx.x * BN;

    if (tid < BN) bias_s[tid] = b_ih[n0 + tid] + b_hh[n0 + tid];

    float acc[4][4];
#pragma unroll
    for (int i = 0; i < 4; i++)
#pragma unroll
        for (int j = 0; j < 4; j++) acc[i][j] = 0.f;

    for (int kt = 0; kt < 256; kt += BK) {
        __syncthreads();
#pragma unroll
        for (int r = 0; r < 2; r++) {
            int v   = tid + r * 256;
            int row = v >> 3;          // 0..63
            int kc  = v & 7;           // 0..7 (float4 within 32-wide k tile)
            float4 a4 = *(const float4*)&x   [(m0 + row) * 256 + kt + kc * 4];
            float4 b4 = *(const float4*)&W_ih[((long)(n0 + row)) * 256 + kt + kc * 4];
            As[(kc * 4 + 0) * PAD + row] = a4.x;
            As[(kc * 4 + 1) * PAD + row] = a4.y;
            As[(kc * 4 + 2) * PAD + row] = a4.z;
            As[(kc * 4 + 3) * PAD + row] = a4.w;
            Bs[(kc * 4 + 0) * PAD + row] = b4.x;
            Bs[(kc * 4 + 1) * PAD + row] = b4.y;
            Bs[(kc * 4 + 2) * PAD + row] = b4.z;
            Bs[(kc * 4 + 3) * PAD + row] = b4.w;
        }
        __syncthreads();
#pragma unroll
        for (int k = 0; k < BK; k++) {
            float4 a4 = *(float4*)&As[k * PAD + ty * 4];
            float4 b4 = *(float4*)&Bs[k * PAD + tx * 4];
            float av[4] = {a4.x, a4.y, a4.z, a4.w};
            float bv[4] = {b4.x, b4.y, b4.z, b4.w};
#pragma unroll
            for (int i = 0; i < 4; i++)
#pragma unroll
                for (int j = 0; j < 4; j++) acc[i][j] += av[i] * bv[j];
        }
    }

#pragma unroll
    for (int i = 0; i < 4; i++) {
        long m = m0 + ty * 4 + i;
        float4 o;
        o.x = acc[i][0] + bias_s[tx * 4 + 0];
        o.y = acc[i][1] + bias_s[tx * 4 + 1];
        o.z = acc[i][2] + bias_s[tx * 4 + 2];
        o.w = acc[i][3] + bias_s[tx * 4 + 3];
        *(float4*)&g_xproj[m * G4 + n0 + tx * 4] = o;
    }
}

// ======================= Phase 2: persistent LSTM recurrence =================
// 128 CTAs = 16 batch-groups(4 batches) x 8 hidden-groups(32 hidden = 128 gate rows)
// CTA keeps its 128x256 W_hh slice in smem (k-major) and its c slice in regs.
#define GRID2 128
#define T2    128

__device__ __forceinline__ float sigm_f(float x) {
    return 1.f / (1.f + __expf(-x));
}
__device__ __forceinline__ float tanh_f(float x) {
    return 2.f / (1.f + __expf(-2.f * x)) - 1.f;
}

__global__ __launch_bounds__(T2, 1) void lstm_kernel(
    const float* __restrict__ W_hh, float* __restrict__ out, int write_state)
{
    extern __shared__ float sm[];
    float* W_s     = sm;                    // [256][128]  W_s[k*128 + r_local]
    float* h_s     = W_s + 256 * 128;       // [256][4]    h_s[k*4 + b]
    float* gates_s = h_s + 256 * 4;         // [128][4]    gates_s[r_local*4 + b]
    __shared__ unsigned gen0_s;

    const int tid   = threadIdx.x;
    const int bg    = blockIdx.x >> 3;      // 0..15
    const int hg    = blockIdx.x & 7;       // 0..7
    const int bbase = bg * 4;
    const int jbase = hg * 32;
    const int q     = tid >> 5;             // gate index 0..3 (i,f,g,o)
    const int jl    = tid & 31;             // hidden within group
    const int row   = q * 256 + jbase + jl; // global gate row (W_hh row)

    // one-time: stage W_hh slice into smem, k-major
    {
        const float4* wrow = (const float4*)&W_hh[(long)row * 256];
#pragma unroll 4
        for (int k4 = 0; k4 < 64; k4++) {
            float4 w = wrow[k4];
            W_s[(k4 * 4 + 0) * 128 + tid] = w.x;
            W_s[(k4 * 4 + 1) * 128 + tid] = w.y;
            W_s[(k4 * 4 + 2) * 128 + tid] = w.z;
            W_s[(k4 * 4 + 3) * 128 + tid] = w.w;
        }
    }

    if (tid == 0) gen0_s = *((volatile unsigned*)&g_gen);
    __syncthreads();
    const unsigned gen0 = gen0_s;

    // per-thread x_proj base pointers (4 batches, this thread's gate row)
    const float* xp_p[4];
#pragma unroll
    for (int b = 0; b < 4; b++)
        xp_p[b] = &g_xproj[((long)(bbase + b) * SS) * G4 + row];

    float c_reg = 0.f;       // c for (b = tid>>5, j = tid&31) of this block
    float h_last = 0.f;

    for (int t = 0; t < SS; t++) {
        // prefetch x_proj for this thread's gate row, 4 batches
        float xp[4];
#pragma unroll
        for (int b = 0; b < 4; b++)
            xp[b] = xp_p[b][(long)t * G4];

        // stage h (prev step) for our 4 batches
        const int p = t & 1;
        if (t == 0) {
            for (int i = tid; i < 1024; i += T2) h_s[i] = 0.f;
        } else {
            for (int i = tid; i < 1024; i += T2) {
                int b = i >> 8, k = i & 255;
                h_s[k * 4 + b] = g_h[p][(bbase + b) * HH + k];
            }
        }
        __syncthreads();

        // gates[b] = xp[b] + sum_k W[row,k] * h[b,k]
        float a0 = xp[0], a1 = xp[1], a2 = xp[2], a3 = xp[3];
#pragma unroll 8
        for (int k = 0; k < 256; k++) {
            float  w  = W_s[k * 128 + tid];
            float4 h4 = *(float4*)&h_s[k * 4];
            a0 += w * h4.x; a1 += w * h4.y; a2 += w * h4.z; a3 += w * h4.w;
        }
        gates_s[tid * 4 + 0] = a0;
        gates_s[tid * 4 + 1] = a1;
        gates_s[tid * 4 + 2] = a2;
        gates_s[tid * 4 + 3] = a3;
        __syncthreads();

        // elementwise update: thread owns (b = tid>>5, j = tid&31)
        {
            const int b = tid >> 5, j = tid & 31;
            float gi = gates_s[(     j) * 4 + b];
            float gf = gates_s[(32 + j) * 4 + b];
            float gg = gates_s[(64 + j) * 4 + b];
            float go = gates_s[(96 + j) * 4 + b];
            float iv = sigm_f(gi);
            float fv = sigm_f(gf);
            float gv = tanh_f(gg);
            float ov = sigm_f(go);
            c_reg = fv * c_reg + iv * gv;
            float hn = ov * tanh_f(c_reg);
            h_last = hn;
            g_h[p ^ 1][(bbase + b) * HH + jbase + j] = hn;
            out[(((long)(bbase + b)) * SS + t) * HH + jbase + j] = hn;
        }

        // ---- grid-wide barrier (sense via monotone generation counter) ----
        __threadfence();
        __syncthreads();
        if (tid == 0) {
            unsigned a = atomicAdd(&g_cnt, 1);
            if (a == GRID2 - 1) {
                g_cnt = 0;
                __threadfence();
                atomicAdd(&g_gen, 1);
            } else {
                while ((*((volatile unsigned*)&g_gen) - gen0) < (unsigned)(t + 1))
                    __nanosleep(64);
            }
        }
        __syncthreads();
    }

    if (write_state) {
        const int b = tid >> 5, j = tid & 31;
        const long hoff = (long)BB * SS * HH;
        out[hoff +           (bbase + b) * HH + jbase + j] = h_last;
        out[hoff + BB * HH + (bbase + b) * HH + jbase + j] = c_reg;
    }
}

// ============================= launch ========================================
extern "C" void kernel_launch(void* const* d_in, const int* in_sizes, int n_in,
                              void* d_out, int out_size)
{
    const float* x    = (const float*)d_in[0];  // [64,2048,256]
    const float* W_ih = (const float*)d_in[1];  // [1024,256]
    const float* W_hh = (const float*)d_in[2];  // [1024,256]
    const float* b_ih = (const float*)d_in[3];  // [1024]
    const float* b_hh = (const float*)d_in[4];  // [1024]
    float* out = (float*)d_out;

    // Phase 1: x_proj
    dim3 g1(G4 / BN, MTOT / BM);   // (16, 2048)
    xproj_kernel<<<g1, 256>>>(x, W_ih, b_ih, b_hh);

    // Phase 2: persistent recurrence (set smem attr unconditionally — no static
    // guards allowed; this is a host-side attribute set, legal during capture)
    const int smem_bytes = (256 * 128 + 256 * 4 + 128 * 4) * (int)sizeof(float);
    cudaFuncSetAttribute(lstm_kernel,
                         cudaFuncAttributeMaxDynamicSharedMemorySize,
                         smem_bytes);
    const long full = (long)BB * SS * HH + 2L * BB * HH;
    int write_state = ((long)out_size >= full) ? 1 : 0;
    lstm_kernel<<<GRID2, T2, smem_bytes>>>(W_hh, out, write_state);
}

// round 4
// speedup vs baseline: 1.1420x; 1.1420x over previous
#include <cuda_runtime.h>
#include <cstdint>

#define BB   64
#define SS   2048
#define HH   256
#define G4   1024
#define MTOT (BB*SS)

// ---------------- scratch (device globals) -----------------------------------
__device__ float    g_xproj[(size_t)MTOT * G4];   // [B*S, 4H] (512 MB)
__device__ float    g_h[2][16 * 1024];            // [parity][bg][k2*8 + b*2 + par]
__device__ unsigned g_cnt2[16 * 32];              // per-bg arrive counters (128B apart)
__device__ unsigned g_gen2[16 * 32];              // per-bg generation (monotone)

// ---------------- f32x2 packed helpers (sm_103a) -----------------------------
__device__ __forceinline__ void ffma2(unsigned long long& d,
                                      unsigned long long a, unsigned long long b) {
    asm("fma.rn.f32x2 %0, %1, %2, %3;" : "=l"(d) : "l"(a), "l"(b), "l"(d));
}
__device__ __forceinline__ unsigned long long pack2(float x, float y) {
    unsigned long long r;
    asm("mov.b64 %0, {%1, %2};" : "=l"(r) : "f"(x), "f"(y));
    return r;
}
__device__ __forceinline__ void unpack2(unsigned long long v, float& a, float& b) {
    asm("mov.b64 {%0, %1}, %2;" : "=f"(a), "=f"(b) : "l"(v));
}
__device__ __forceinline__ float sum2(unsigned long long v) {
    float a, b; unpack2(v, a, b); return a + b;
}

// ======================= Phase 1: x_proj GEMM ================================
// C[m,n] = sum_k x[m,k]*W_ih[n,k] + bias[n];  M=131072, N=1024, K=256
// 128x128x16 tile, 256 threads, 8x8 microtile (4+4 split), f32x2 packed over n.
#define P1T  256
#define PBM  128
#define PBN  128
#define PBK  16
#define PPAD 132   // floats per k-row (128 + 4), keeps 16B alignment

__global__ __launch_bounds__(P1T, 2) void xproj_kernel(
    const float* __restrict__ x, const float* __restrict__ W_ih,
    const float* __restrict__ b_ih, const float* __restrict__ b_hh)
{
    __shared__ float As[PBK * PPAD];   // [k][m]
    __shared__ float Bs[PBK * PPAD];   // [k][n]

    const int tid = threadIdx.x;
    const int tx  = tid & 15;          // n quadrant
    const int ty  = tid >> 4;          // m quadrant
    const long m0 = (long)blockIdx.y * PBM;
    const int  n0 = blockIdx.x * PBN;
    const int  lm = tid >> 1;          // global-load row within tile (0..127)
    const int  lh = tid & 1;           // k half (8 floats each)

    unsigned long long acc[8][4];
#pragma unroll
    for (int i = 0; i < 8; i++)
#pragma unroll
        for (int j = 0; j < 4; j++) acc[i][j] = 0ull;

    for (int kt = 0; kt < 256; kt += PBK) {
        __syncthreads();
        {
            const float* xa = &x   [(m0 + lm) * 256 + kt + lh * 8];
            const float* wb = &W_ih[((long)(n0 + lm)) * 256 + kt + lh * 8];
            float4 a0 = *(const float4*)&xa[0];
            float4 a1 = *(const float4*)&xa[4];
            float4 c0 = *(const float4*)&wb[0];
            float4 c1 = *(const float4*)&wb[4];
            int kb = lh * 8;
            As[(kb + 0) * PPAD + lm] = a0.x;  As[(kb + 1) * PPAD + lm] = a0.y;
            As[(kb + 2) * PPAD + lm] = a0.z;  As[(kb + 3) * PPAD + lm] = a0.w;
            As[(kb + 4) * PPAD + lm] = a1.x;  As[(kb + 5) * PPAD + lm] = a1.y;
            As[(kb + 6) * PPAD + lm] = a1.z;  As[(kb + 7) * PPAD + lm] = a1.w;
            Bs[(kb + 0) * PPAD + lm] = c0.x;  Bs[(kb + 1) * PPAD + lm] = c0.y;
            Bs[(kb + 2) * PPAD + lm] = c0.z;  Bs[(kb + 3) * PPAD + lm] = c0.w;
            Bs[(kb + 4) * PPAD + lm] = c1.x;  Bs[(kb + 5) * PPAD + lm] = c1.y;
            Bs[(kb + 6) * PPAD + lm] = c1.z;  Bs[(kb + 7) * PPAD + lm] = c1.w;
        }
        __syncthreads();
#pragma unroll
        for (int k = 0; k < PBK; k++) {
            const float* ar = &As[k * PPAD];
            const float* br = &Bs[k * PPAD];
            float4 a0 = *(const float4*)&ar[ty * 4];
            float4 a1 = *(const float4*)&ar[64 + ty * 4];
            float4 bq0 = *(const float4*)&br[tx * 4];
            float4 bq1 = *(const float4*)&br[64 + tx * 4];
            unsigned long long bp[4];
            bp[0] = pack2(bq0.x, bq0.y);
            bp[1] = pack2(bq0.z, bq0.w);
            bp[2] = pack2(bq1.x, bq1.y);
            bp[3] = pack2(bq1.z, bq1.w);
            float am[8] = {a0.x, a0.y, a0.z, a0.w, a1.x, a1.y, a1.z, a1.w};
#pragma unroll
            for (int mi = 0; mi < 8; mi++) {
                unsigned long long ad = pack2(am[mi], am[mi]);
#pragma unroll
                for (int nj = 0; nj < 4; nj++) ffma2(acc[mi][nj], ad, bp[nj]);
            }
        }
    }

    // epilogue: bias + store
    float bias[8];
    {
        float4 i0 = *(const float4*)&b_ih[n0 + tx * 4];
        float4 i1 = *(const float4*)&b_ih[n0 + 64 + tx * 4];
        float4 h0 = *(const float4*)&b_hh[n0 + tx * 4];
        float4 h1 = *(const float4*)&b_hh[n0 + 64 + tx * 4];
        bias[0] = i0.x + h0.x; bias[1] = i0.y + h0.y;
        bias[2] = i0.z + h0.z; bias[3] = i0.w + h0.w;
        bias[4] = i1.x + h1.x; bias[5] = i1.y + h1.y;
        bias[6] = i1.z + h1.z; bias[7] = i1.w + h1.w;
    }
#pragma unroll
    for (int mi = 0; mi < 8; mi++) {
        long m = m0 + ((mi < 4) ? (ty * 4 + mi) : (64 + ty * 4 + mi - 4));
        float v0, v1, v2, v3;
        float4 o;
        unpack2(acc[mi][0], v0, v1); unpack2(acc[mi][1], v2, v3);
        o.x = v0 + bias[0]; o.y = v1 + bias[1]; o.z = v2 + bias[2]; o.w = v3 + bias[3];
        *(float4*)&g_xproj[m * G4 + n0 + tx * 4] = o;
        unpack2(acc[mi][2], v0, v1); unpack2(acc[mi][3], v2, v3);
        o.x = v0 + bias[4]; o.y = v1 + bias[5]; o.z = v2 + bias[6]; o.w = v3 + bias[7];
        *(float4*)&g_xproj[m * G4 + n0 + 64 + tx * 4] = o;
    }
}

// ======================= Phase 2: persistent LSTM recurrence =================
// 128 CTAs = 16 bg (4 batches) x 8 hg (32 hidden = 128 gate rows).
// W_hh slice in smem as k-pairs (f32x2), c in regs, per-bg 8-CTA barrier.
#define GRID2 128
#define T2    256

__device__ __forceinline__ float sigm_f(float x) { return 1.f / (1.f + __expf(-x)); }
__device__ __forceinline__ float tanh_f(float x) { return 2.f / (1.f + __expf(-2.f * x)) - 1.f; }

__global__ __launch_bounds__(T2, 1) void lstm_kernel(
    const float* __restrict__ W_hh, float* __restrict__ out, int write_state)
{
    extern __shared__ float sm[];
    float2* W2    = (float2*)sm;              // [k2=128][r=128] float2  (128 KB)
    float*  h2    = sm + 2 * 128 * 128;       // [k2=128][8]: b*2+par    (4 KB)
    float*  gates = h2 + 1024;                // [128][5]                (2.5 KB)
    __shared__ unsigned gen0_s;

    const int tid   = threadIdx.x;
    const int r     = tid & 127;              // local gate row
    const int bh    = tid >> 7;               // batch half: handles {2bh, 2bh+1}
    const int bg    = blockIdx.x >> 3;        // 0..15
    const int hg    = blockIdx.x & 7;         // 0..7
    const int bbase = bg * 4;
    const int jbase = hg * 32;
    const int q     = r >> 5;                 // gate 0..3 (i,f,g,o)
    const int jl    = r & 31;
    const int row   = q * 256 + jbase + jl;   // global W_hh row

    // one-time: stage W_hh slice as k-pairs; thread covers its k-half
    {
        const float4* wr = (const float4*)&W_hh[(long)row * 256];
        for (int k4 = bh * 32; k4 < bh * 32 + 32; k4++) {
            float4 w = wr[k4];
            W2[(2 * k4 + 0) * 128 + r] = make_float2(w.x, w.y);
            W2[(2 * k4 + 1) * 128 + r] = make_float2(w.z, w.w);
        }
    }

    if (tid == 0) gen0_s = *((volatile unsigned*)&g_gen2[bg * 32]);
    __syncthreads();
    const unsigned gen0 = gen0_s;

    const float* xpp0 = &g_xproj[((long)(bbase + 2 * bh + 0) * SS) * G4 + row];
    const float* xpp1 = &g_xproj[((long)(bbase + 2 * bh + 1) * SS) * G4 + row];
    float xp0 = __ldcg(xpp0);
    float xp1 = __ldcg(xpp1);

    float c_reg = 0.f, h_last = 0.f;

    for (int t = 0; t < SS; t++) {
        const int p = t & 1;
        // stage h(t-1): layout in gmem matches h2 exactly -> float4 copy
        if (t == 0) {
            *(float4*)&h2[tid * 4] = make_float4(0.f, 0.f, 0.f, 0.f);
        } else {
            float4 hv = __ldcg((const float4*)&g_h[p][bg * 1024 + tid * 4]);
            *(float4*)&h2[tid * 4] = hv;
        }
        __syncthreads();

        // gates for (row r) x (batches 2bh,2bh+1): packed over k parity
        unsigned long long a0 = 0ull, a1 = 0ull;
#pragma unroll 8
        for (int k2 = 0; k2 < 128; k2++) {
            unsigned long long wb = *(const unsigned long long*)&W2[k2 * 128 + r];
            ulonglong2 hp = *(const ulonglong2*)&h2[k2 * 8 + 4 * bh];
            ffma2(a0, wb, hp.x);
            ffma2(a1, wb, hp.y);
        }
        gates[r * 5 + 2 * bh + 0] = xp0 + sum2(a0);
        gates[r * 5 + 2 * bh + 1] = xp1 + sum2(a1);

        // prefetch next step's x_proj behind sync/elementwise/barrier shadow
        if (t + 1 < SS) {
            xp0 = __ldcg(xpp0 + (long)(t + 1) * G4);
            xp1 = __ldcg(xpp1 + (long)(t + 1) * G4);
        }
        __syncthreads();

        if (tid < 128) {
            const int b = tid >> 5, j = tid & 31;
            float gi = gates[(     j) * 5 + b];
            float gf = gates[(32 + j) * 5 + b];
            float gg = gates[(64 + j) * 5 + b];
            float go = gates[(96 + j) * 5 + b];
            float iv = sigm_f(gi);
            float fv = sigm_f(gf);
            float gv = tanh_f(gg);
            float ov = sigm_f(go);
            c_reg = fv * c_reg + iv * gv;
            float hn = ov * tanh_f(c_reg);
            h_last = hn;
            const int kh = jbase + j;
            g_h[p ^ 1][bg * 1024 + (kh >> 1) * 8 + b * 2 + (kh & 1)] = hn;
            out[(((long)(bbase + b)) * SS + t) * HH + kh] = hn;
        }

        // ---- per-bg barrier: 8 CTAs, monotone generation ----
        __threadfence();
        __syncthreads();
        if (tid == 0) {
            unsigned a = atomicAdd(&g_cnt2[bg * 32], 1);
            if (a == 7) {
                g_cnt2[bg * 32] = 0;
                __threadfence();
                atomicAdd(&g_gen2[bg * 32], 1);
            } else {
                while ((*((volatile unsigned*)&g_gen2[bg * 32]) - gen0) <
                       (unsigned)(t + 1)) { }
            }
            __threadfence();
        }
        __syncthreads();
    }

    if (write_state && tid < 128) {
        const int b = tid >> 5, j = tid & 31;
        const long hoff = (long)BB * SS * HH;
        out[hoff +           (bbase + b) * HH + jbase + j] = h_last;
        out[hoff + BB * HH + (bbase + b) * HH + jbase + j] = c_reg;
    }
}

// ============================= launch ========================================
extern "C" void kernel_launch(void* const* d_in, const int* in_sizes, int n_in,
                              void* d_out, int out_size)
{
    const float* x    = (const float*)d_in[0];
    const float* W_ih = (const float*)d_in[1];
    const float* W_hh = (const float*)d_in[2];
    const float* b_ih = (const float*)d_in[3];
    const float* b_hh = (const float*)d_in[4];
    float* out = (float*)d_out;

    dim3 g1(G4 / PBN, MTOT / PBM);   // (8, 1024)
    xproj_kernel<<<g1, P1T>>>(x, W_ih, b_ih, b_hh);

    const int smem_bytes = (2 * 128 * 128 + 1024 + 128 * 5) * (int)sizeof(float);
    cudaFuncSetAttribute(lstm_kernel,
                         cudaFuncAttributeMaxDynamicSharedMemorySize, smem_bytes);
    const long full = (long)BB * SS * HH + 2L * BB * HH;
    int write_state = ((long)out_size >= full) ? 1 : 0;
    lstm_kernel<<<GRID2, T2, smem_bytes>>>(W_hh, out, write_state);
}